// round 7
// baseline (speedup 1.0000x reference)
#include <cuda_runtime.h>
#include <cuda_bf16.h>
#include <cstdint>

// ============================================================================
// Compile-time reproduction of np.random.RandomState(0) op sequence
// ============================================================================
struct OpT { int kind; int a; int b; };   // kind: 0=rx 1=ry 2=rz 3=cnot
struct MTc { unsigned mt[624]; int mti; };

constexpr unsigned mt_next(MTc &s) {
    if (s.mti >= 624) {
        for (int i = 0; i < 624; ++i) {
            unsigned y = (s.mt[i] & 0x80000000u) | (s.mt[(i + 1) % 624] & 0x7fffffffu);
            unsigned v = s.mt[(i + 397) % 624] ^ (y >> 1);
            if (y & 1u) v ^= 0x9908b0dfu;
            s.mt[i] = v;
        }
        s.mti = 0;
    }
    unsigned y = s.mt[s.mti++];
    y ^= y >> 11;
    y ^= (y << 7)  & 0x9d2c5680u;
    y ^= (y << 15) & 0xefc60000u;
    y ^= y >> 18;
    return y;
}
constexpr unsigned mt_interval(MTc &s, unsigned maxv) {
    unsigned mask = maxv;
    mask |= mask >> 1; mask |= mask >> 2; mask |= mask >> 4;
    mask |= mask >> 8; mask |= mask >> 16;
    unsigned v = mt_next(s) & mask;
    while (v > maxv) v = mt_next(s) & mask;
    return v;
}
struct Ops { OpT ops[20]; };
constexpr Ops make_ops() {
    Ops o{};
    MTc s{};
    s.mt[0] = 0u;
    for (int i = 1; i < 624; ++i)
        s.mt[i] = 1812433253u * (s.mt[i - 1] ^ (s.mt[i - 1] >> 30)) + (unsigned)i;
    s.mti = 624;
    for (int i = 0; i < 20; ++i) {
        unsigned k = mt_interval(s, 3u);
        if (k == 3u) {
            int perm[8] = {0,1,2,3,4,5,6,7};
            for (int j = 7; j >= 1; --j) {
                unsigned x = mt_interval(s, (unsigned)j);
                int t = perm[j]; perm[j] = perm[x]; perm[x] = t;
            }
            o.ops[i] = OpT{3, perm[0], perm[1]};
        } else {
            unsigned w = mt_interval(s, 7u);
            o.ops[i] = OpT{(int)k, (int)w, 0};
        }
    }
    return o;
}
constexpr Ops OPS = make_ops();

// ============================================================================
// Compile-time wire -> bit map: put the 3 wires with highest cross-lane
// (shuffle) cost into register bits p=0,1,2; rest on lane bits p=3..7.
// shfl cost model: rx/ry rotation = 16, cnot target = 8, rz/cnot-ctrl = 0.
// ============================================================================
struct Map { int pmap[8]; };
constexpr Map make_map() {
    int cost[8] = {};
    for (int i = 0; i < 20; ++i) {
        OpT op = OPS.ops[i];
        if (op.kind == 3)      cost[op.b] += 8;
        else if (op.kind != 2) cost[op.a] += 16;
    }
    Map m{};
    bool isreg[8] = {};
    for (int p = 0; p < 3; ++p) {
        int best = 0, bc = -1;
        for (int w = 0; w < 8; ++w)
            if (!isreg[w] && cost[w] > bc) { bc = cost[w]; best = w; }
        isreg[best] = true; m.pmap[best] = p;
    }
    int lp = 3;
    for (int w = 0; w < 8; ++w) if (!isreg[w]) m.pmap[w] = lp++;
    return m;
}
constexpr Map MAP = make_map();
constexpr int wire_of(int p) {
    for (int w = 0; w < 8; ++w) if (MAP.pmap[w] == p) return w;
    return 0;
}
// all accesses below are constant-expression scalars (safe in device code)
constexpr int RW0 = wire_of(0), RW1 = wire_of(1), RW2 = wire_of(2);
constexpr int LW0 = wire_of(3), LW1 = wire_of(4), LW2 = wire_of(5),
              LW3 = wire_of(6), LW4 = wire_of(7);

// ============================================================================
// Packed fp32x2 helpers
// ============================================================================
__device__ __forceinline__ float2 f2mul(float2 a, float2 b) {
    float2 d;
    asm("{\n\t"
        ".reg .b64 ra, rb, rd;\n\t"
        "mov.b64 ra, {%2, %3};\n\t"
        "mov.b64 rb, {%4, %5};\n\t"
        "mul.rn.f32x2 rd, ra, rb;\n\t"
        "mov.b64 {%0, %1}, rd;\n\t"
        "}"
        : "=f"(d.x), "=f"(d.y)
        : "f"(a.x), "f"(a.y), "f"(b.x), "f"(b.y));
    return d;
}
__device__ __forceinline__ float2 f2fma(float2 a, float2 b, float2 c) {
    float2 d;
    asm("{\n\t"
        ".reg .b64 ra, rb, rc, rd;\n\t"
        "mov.b64 ra, {%2, %3};\n\t"
        "mov.b64 rb, {%4, %5};\n\t"
        "mov.b64 rc, {%6, %7};\n\t"
        "fma.rn.f32x2 rd, ra, rb, rc;\n\t"
        "mov.b64 {%0, %1}, rd;\n\t"
        "}"
        : "=f"(d.x), "=f"(d.y)
        : "f"(a.x), "f"(a.y), "f"(b.x), "f"(b.y), "f"(c.x), "f"(c.y));
    return d;
}
__device__ __forceinline__ float2 f2add(float2 a, float2 b) {
    float2 d;
    asm("{\n\t"
        ".reg .b64 ra, rb, rd;\n\t"
        "mov.b64 ra, {%2, %3};\n\t"
        "mov.b64 rb, {%4, %5};\n\t"
        "add.rn.f32x2 rd, ra, rb;\n\t"
        "mov.b64 {%0, %1}, rd;\n\t"
        "}"
        : "=f"(d.x), "=f"(d.y)
        : "f"(a.x), "f"(a.y), "f"(b.x), "f"(b.y));
    return d;
}
__device__ __forceinline__ float2 shfl_xor2(float2 v, int m) {
    v.x = __shfl_xor_sync(0xffffffffu, v.x, m);
    v.y = __shfl_xor_sync(0xffffffffu, v.y, m);
    return v;
}

// ============================================================================
// Packed gate application. Amp index bit p = MAP.pmap[wire] (constexpr).
// p==0 -> pack half; p in {1,2} -> pack bit p-1; p>=3 -> lane bit p-3.
// ============================================================================
template<int KIND, int A, int B>
__device__ __forceinline__ void gateP(float2 (&RE)[4], float2 (&IM)[4], int lane,
                                      float cc, float ss) {
    constexpr unsigned FULL = 0xffffffffu;
    if constexpr (KIND == 3) {                       // CNOT ctrl A tgt B
        constexpr int pc = MAP.pmap[A], pt = MAP.pmap[B];
        if constexpr (pc < 3 && pt < 3) {
            if constexpr (pt == 0) {
                constexpr int cb = pc - 1;
                #pragma unroll
                for (int k = 0; k < 4; ++k)
                    if ((k >> cb) & 1) {
                        RE[k] = make_float2(RE[k].y, RE[k].x);
                        IM[k] = make_float2(IM[k].y, IM[k].x);
                    }
            } else if constexpr (pc == 0) {
                constexpr int tb = pt - 1, mm = 1 << tb;
                #pragma unroll
                for (int k = 0; k < 4; ++k)
                    if (!((k >> tb) & 1)) {
                        int q = k + mm;
                        float t = RE[k].y; RE[k].y = RE[q].y; RE[q].y = t;
                        t = IM[k].y; IM[k].y = IM[q].y; IM[q].y = t;
                    }
            } else {
                constexpr int cb = pc - 1, tb = pt - 1, mm = 1 << tb;
                #pragma unroll
                for (int k = 0; k < 4; ++k)
                    if (((k >> cb) & 1) && !((k >> tb) & 1)) {
                        float2 t = RE[k]; RE[k] = RE[k + mm]; RE[k + mm] = t;
                        t = IM[k]; IM[k] = IM[k + mm]; IM[k + mm] = t;
                    }
            }
        } else if constexpr (pc < 3 && pt >= 3) {
            constexpr int ml = 1 << (pt - 3);
            if constexpr (pc == 0) {
                #pragma unroll
                for (int k = 0; k < 4; ++k) {
                    RE[k].y = __shfl_xor_sync(FULL, RE[k].y, ml);
                    IM[k].y = __shfl_xor_sync(FULL, IM[k].y, ml);
                }
            } else {
                constexpr int cb = pc - 1;
                #pragma unroll
                for (int k = 0; k < 4; ++k)
                    if ((k >> cb) & 1) {
                        RE[k] = shfl_xor2(RE[k], ml);
                        IM[k] = shfl_xor2(IM[k], ml);
                    }
            }
        } else if constexpr (pc >= 3 && pt < 3) {
            bool bc = (lane >> (pc - 3)) & 1;
            if constexpr (pt == 0) {
                #pragma unroll
                for (int k = 0; k < 4; ++k) {
                    float2 v = RE[k];
                    RE[k] = bc ? make_float2(v.y, v.x) : v;
                    float2 u = IM[k];
                    IM[k] = bc ? make_float2(u.y, u.x) : u;
                }
            } else {
                constexpr int tb = pt - 1, mm = 1 << tb;
                #pragma unroll
                for (int k = 0; k < 4; ++k)
                    if (!((k >> tb) & 1)) {
                        int q = k + mm;
                        float2 a = RE[k], b2v = RE[q];
                        RE[k] = bc ? b2v : a; RE[q] = bc ? a : b2v;
                        float2 c2 = IM[k], d2 = IM[q];
                        IM[k] = bc ? d2 : c2; IM[q] = bc ? c2 : d2;
                    }
            }
        } else {
            int bc = (lane >> (pc - 3)) & 1;
            int src = lane ^ (bc << (pt - 3));
            #pragma unroll
            for (int k = 0; k < 4; ++k) {
                RE[k].x = __shfl_sync(FULL, RE[k].x, src);
                RE[k].y = __shfl_sync(FULL, RE[k].y, src);
                IM[k].x = __shfl_sync(FULL, IM[k].x, src);
                IM[k].y = __shfl_sync(FULL, IM[k].y, src);
            }
        }
    } else if constexpr (KIND == 2) {                // RZ
        constexpr int p = MAP.pmap[A];
        float2 C = make_float2(cc, cc);
        if constexpr (p == 0) {
            float2 SE  = make_float2(-ss,  ss);
            float2 NSE = make_float2( ss, -ss);
            #pragma unroll
            for (int k = 0; k < 4; ++k) {
                float2 r0 = f2fma(NSE, IM[k], f2mul(C, RE[k]));
                IM[k] = f2fma(SE, RE[k], f2mul(C, IM[k]));
                RE[k] = r0;
            }
        } else if constexpr (p < 3) {
            constexpr int kb = p - 1;
            float2 SP = make_float2( ss,  ss);
            float2 SN = make_float2(-ss, -ss);
            #pragma unroll
            for (int k = 0; k < 4; ++k) {
                float2 SE  = ((k >> kb) & 1) ? SP : SN;
                float2 NSE = ((k >> kb) & 1) ? SN : SP;
                float2 r0 = f2fma(NSE, IM[k], f2mul(C, RE[k]));
                IM[k] = f2fma(SE, RE[k], f2mul(C, IM[k]));
                RE[k] = r0;
            }
        } else {
            float se = ((lane >> (p - 3)) & 1) ? ss : -ss;
            float2 SE  = make_float2( se,  se);
            float2 NSE = make_float2(-se, -se);
            #pragma unroll
            for (int k = 0; k < 4; ++k) {
                float2 r0 = f2fma(NSE, IM[k], f2mul(C, RE[k]));
                IM[k] = f2fma(SE, RE[k], f2mul(C, IM[k]));
                RE[k] = r0;
            }
        }
    } else if constexpr (KIND == 0) {                // RX
        constexpr int p = MAP.pmap[A];
        float2 C  = make_float2(cc, cc);
        float2 S  = make_float2( ss,  ss);
        float2 NS = make_float2(-ss, -ss);
        if constexpr (p == 0) {
            #pragma unroll
            for (int k = 0; k < 4; ++k) {
                float2 isw = make_float2(IM[k].y, IM[k].x);
                float2 rsw = make_float2(RE[k].y, RE[k].x);
                RE[k] = f2fma(S,  isw, f2mul(C, RE[k]));
                IM[k] = f2fma(NS, rsw, f2mul(C, IM[k]));
            }
        } else if constexpr (p < 3) {
            constexpr int kb = p - 1, mm = 1 << kb;
            #pragma unroll
            for (int k = 0; k < 4; ++k)
                if (!((k >> kb) & 1)) {
                    int q = k + mm;
                    float2 rk = RE[k], ik = IM[k], rq = RE[q], iq = IM[q];
                    RE[k] = f2fma(S,  iq, f2mul(C, rk));
                    IM[k] = f2fma(NS, rq, f2mul(C, ik));
                    RE[q] = f2fma(S,  ik, f2mul(C, rq));
                    IM[q] = f2fma(NS, rk, f2mul(C, iq));
                }
        } else {
            constexpr int m = 1 << (p - 3);
            #pragma unroll
            for (int k = 0; k < 4; ++k) {
                float2 pr = shfl_xor2(RE[k], m);
                float2 pi = shfl_xor2(IM[k], m);
                RE[k] = f2fma(S,  pi, f2mul(C, RE[k]));
                IM[k] = f2fma(NS, pr, f2mul(C, IM[k]));
            }
        }
    } else {                                         // RY
        constexpr int p = MAP.pmap[A];
        float2 C = make_float2(cc, cc);
        if constexpr (p == 0) {
            float2 MS = make_float2(-ss, ss);
            #pragma unroll
            for (int k = 0; k < 4; ++k) {
                float2 rsw = make_float2(RE[k].y, RE[k].x);
                float2 isw = make_float2(IM[k].y, IM[k].x);
                RE[k] = f2fma(MS, rsw, f2mul(C, RE[k]));
                IM[k] = f2fma(MS, isw, f2mul(C, IM[k]));
            }
        } else if constexpr (p < 3) {
            constexpr int kb = p - 1, mm = 1 << kb;
            float2 S  = make_float2( ss,  ss);
            float2 NS = make_float2(-ss, -ss);
            #pragma unroll
            for (int k = 0; k < 4; ++k)
                if (!((k >> kb) & 1)) {
                    int q = k + mm;
                    float2 rk = RE[k], rq = RE[q];
                    RE[k] = f2fma(NS, rq, f2mul(C, rk));
                    RE[q] = f2fma(S,  rk, f2mul(C, rq));
                    float2 ik = IM[k], iq = IM[q];
                    IM[k] = f2fma(NS, iq, f2mul(C, ik));
                    IM[q] = f2fma(S,  ik, f2mul(C, iq));
                }
        } else {
            constexpr int m = 1 << (p - 3);
            float sg = ((lane >> (p - 3)) & 1) ? ss : -ss;
            float2 SG = make_float2(sg, sg);
            #pragma unroll
            for (int k = 0; k < 4; ++k) {
                float2 pr = shfl_xor2(RE[k], m);
                float2 pi = shfl_xor2(IM[k], m);
                RE[k] = f2fma(SG, pr, f2mul(C, RE[k]));
                IM[k] = f2fma(SG, pi, f2mul(C, IM[k]));
            }
        }
    }
}

template<int I>
__device__ __forceinline__ void apply_opP(float2 (&RE)[4], float2 (&IM)[4], int lane,
                                          const float* cs) {
    gateP<OPS.ops[I].kind, OPS.ops[I].a, OPS.ops[I].b>(RE, IM, lane, cs[2 * I], cs[2 * I + 1]);
}

// per-wire expectation selection, fully compile-time on the bit position
template<int W>
__device__ __forceinline__ float pick_ev(float ehalf, float epk0, float epk1,
                                         float ptot, int lane) {
    constexpr int p = MAP.pmap[W];
    if constexpr (p == 0)      return ehalf;
    else if constexpr (p == 1) return epk0;
    else if constexpr (p == 2) return epk1;
    else return ((lane >> (p - 3)) & 1) ? -ptot : ptot;
}

// ============================================================================
// Fused kernel: 1 block = 64 rows, 256 threads, 3 blocks/SM target.
//  Phase 0: coefficients + per-row feature sincos -> smem
//  Phase 1: warp w simulates rows w*8..w*8+7, writes h as tf32 fragments -> As
//  Phase 2: in-block GEMM 64 x 512 (tf32 mma), 4 N-chunks of 128
// ============================================================================
#define ST2 36

__device__ __forceinline__ uint32_t f2tf32(float f) {
    uint32_t r;
    asm("cvt.rna.tf32.f32 %0, %1;" : "=r"(r) : "f"(f));
    return r;
}

__global__ __launch_bounds__(256, 3)
void fused_kernel(const float* __restrict__ x, const float* __restrict__ W1,
                  const float* __restrict__ b1,
                  const float* __restrict__ rp, const float* __restrict__ ryt,
                  const float* __restrict__ W2, const float* __restrict__ b2,
                  float* __restrict__ out) {
    constexpr unsigned FULL = 0xffffffffu;
    extern __shared__ char smraw[];
    uint2* As = (uint2*)smraw;                  // [64][ST2] h tile (tf32 frag pairs)
    uint2* Bs = As + 64 * ST2;                  // [128][ST2] W2 chunk
    float* fs = (float*)(Bs + 128 * ST2);       // [64][16] feature (c,s) pairs
    float* cs = fs + 64 * 16;                   // [56] gate coefficients

    int t    = threadIdx.x;
    int lane = t & 31;
    int wid  = t >> 5;
    int bm   = blockIdx.x * 64;

    // ---------------- Phase 0: coefficients + feature sincos ----------------
    if (t < 20) {
        float sv, cv; sincosf(__ldg(rp + t) * 0.5f, &sv, &cv);
        cs[2 * t] = cv; cs[2 * t + 1] = sv;
    } else if (t < 28) {
        int w = t - 20;
        float sv, cv; sincosf(__ldg(ryt + w) * 0.5f, &sv, &cv);
        cs[40 + 2 * w] = cv; cs[41 + 2 * w] = sv;
    }
    #pragma unroll
    for (int i = 0; i < 2; ++i) {               // 512 (row, wire) tasks
        int task = i * 256 + t;
        int row = task >> 3, w = task & 7;
        float v = __ldg(x + (size_t)(bm + row) * 512 + w) * 0.5f;
        float sv, cv; __sincosf(v, &sv, &cv);
        fs[row * 16 + 2 * w]     = cv;
        fs[row * 16 + 2 * w + 1] = sv;
    }
    __syncthreads();

    // ---------------- Phase 1: simulate 8 rows per warp ----------------
    for (int r = 0; r < 8; ++r) {
        int row = wid * 8 + r;
        const float4* fp = (const float4*)(fs + row * 16);
        float4 q0 = fp[0], q1 = fp[1], q2 = fp[2], q3 = fp[3];
        float c[8] = {q0.x, q0.z, q1.x, q1.z, q2.x, q2.z, q3.x, q3.z};
        float s[8] = {q0.y, q0.w, q1.y, q1.w, q2.y, q2.w, q3.y, q3.w};

        // product-state init (bit of wire w = amp bit MAP.pmap[w])
        float lf = 1.0f;
        lf *= ((lane >> 0) & 1) ? s[LW0] : c[LW0];
        lf *= ((lane >> 1) & 1) ? s[LW1] : c[LW1];
        lf *= ((lane >> 2) & 1) ? s[LW2] : c[LW2];
        lf *= ((lane >> 3) & 1) ? s[LW3] : c[LW3];
        lf *= ((lane >> 4) & 1) ? s[LW4] : c[LW4];
        float2 RE[4], IM[4];
        float2 CS0 = make_float2(c[RW0], s[RW0]);
        #pragma unroll
        for (int k = 0; k < 4; ++k) {
            float tv = lf * ((k & 1) ? s[RW1] : c[RW1]) * ((k & 2) ? s[RW2] : c[RW2]);
            RE[k] = f2mul(make_float2(tv, tv), CS0);
            IM[k] = make_float2(0.0f, 0.0f);
        }

        apply_opP<0>(RE, IM, lane, cs);   apply_opP<1>(RE, IM, lane, cs);
        apply_opP<2>(RE, IM, lane, cs);   apply_opP<3>(RE, IM, lane, cs);
        apply_opP<4>(RE, IM, lane, cs);   apply_opP<5>(RE, IM, lane, cs);
        apply_opP<6>(RE, IM, lane, cs);   apply_opP<7>(RE, IM, lane, cs);
        apply_opP<8>(RE, IM, lane, cs);   apply_opP<9>(RE, IM, lane, cs);
        apply_opP<10>(RE, IM, lane, cs);  apply_opP<11>(RE, IM, lane, cs);
        apply_opP<12>(RE, IM, lane, cs);  apply_opP<13>(RE, IM, lane, cs);
        apply_opP<14>(RE, IM, lane, cs);  apply_opP<15>(RE, IM, lane, cs);
        apply_opP<16>(RE, IM, lane, cs);  apply_opP<17>(RE, IM, lane, cs);
        apply_opP<18>(RE, IM, lane, cs);  apply_opP<19>(RE, IM, lane, cs);

        // final RY layer (RYs on distinct wires commute)
        gateP<1, 0, 0>(RE, IM, lane, cs[40], cs[41]);
        gateP<1, 1, 0>(RE, IM, lane, cs[42], cs[43]);
        gateP<1, 2, 0>(RE, IM, lane, cs[44], cs[45]);
        gateP<1, 3, 0>(RE, IM, lane, cs[46], cs[47]);
        gateP<1, 4, 0>(RE, IM, lane, cs[48], cs[49]);
        gateP<1, 5, 0>(RE, IM, lane, cs[50], cs[51]);
        gateP<1, 6, 0>(RE, IM, lane, cs[52], cs[53]);
        gateP<1, 7, 0>(RE, IM, lane, cs[54], cs[55]);

        // probabilities
        float2 P[4];
        #pragma unroll
        for (int k = 0; k < 4; ++k)
            P[k] = f2fma(RE[k], RE[k], f2mul(IM[k], IM[k]));

        float2 S01 = f2add(P[0], P[1]);
        float2 S23 = f2add(P[2], P[3]);
        float2 SA  = f2add(S01, S23);
        float2 D01 = f2add(P[0], make_float2(-P[1].x, -P[1].y));
        float2 D23 = f2add(P[2], make_float2(-P[3].x, -P[3].y));
        float ptot  = SA.x + SA.y;
        float ehalf = SA.x - SA.y;                              // p==0
        float epk0  = (D01.x + D01.y) + (D23.x + D23.y);        // p==1
        float epk1  = (S01.x + S01.y) - (S23.x + S23.y);        // p==2

        float2 E0 = make_float2(pick_ev<0>(ehalf, epk0, epk1, ptot, lane),
                                pick_ev<1>(ehalf, epk0, epk1, ptot, lane));
        float2 E1 = make_float2(pick_ev<2>(ehalf, epk0, epk1, ptot, lane),
                                pick_ev<3>(ehalf, epk0, epk1, ptot, lane));
        float2 E2 = make_float2(pick_ev<4>(ehalf, epk0, epk1, ptot, lane),
                                pick_ev<5>(ehalf, epk0, epk1, ptot, lane));
        float2 E3 = make_float2(pick_ev<6>(ehalf, epk0, epk1, ptot, lane),
                                pick_ev<7>(ehalf, epk0, epk1, ptot, lane));
        #pragma unroll
        for (int off = 16; off > 0; off >>= 1) {
            E0 = f2add(E0, shfl_xor2(E0, off));
            E1 = f2add(E1, shfl_xor2(E1, off));
            E2 = f2add(E2, shfl_xor2(E2, off));
            E3 = f2add(E3, shfl_xor2(E3, off));
        }
        float ev[8] = {E0.x, E0.y, E1.x, E1.y, E2.x, E2.y, E3.x, E3.y};

        // layer 1: h = relu(ev @ W1^T + b1)  (W1 L1-resident after first row)
        const float4* w1a = (const float4*)(W1 + (size_t)lane * 8);
        const float4* w1b = (const float4*)(W1 + (size_t)(lane + 32) * 8);
        float4 A0 = __ldg(w1a), A1 = __ldg(w1a + 1);
        float4 V0 = __ldg(w1b), V1 = __ldg(w1b + 1);
        float h0 = __ldg(b1 + lane), h1 = __ldg(b1 + lane + 32);
        h0 = fmaf(A0.x, ev[0], h0); h0 = fmaf(A0.y, ev[1], h0);
        h0 = fmaf(A0.z, ev[2], h0); h0 = fmaf(A0.w, ev[3], h0);
        h0 = fmaf(A1.x, ev[4], h0); h0 = fmaf(A1.y, ev[5], h0);
        h0 = fmaf(A1.z, ev[6], h0); h0 = fmaf(A1.w, ev[7], h0);
        h1 = fmaf(V0.x, ev[0], h1); h1 = fmaf(V0.y, ev[1], h1);
        h1 = fmaf(V0.z, ev[2], h1); h1 = fmaf(V0.w, ev[3], h1);
        h1 = fmaf(V1.x, ev[4], h1); h1 = fmaf(V1.y, ev[5], h1);
        h1 = fmaf(V1.z, ev[6], h1); h1 = fmaf(V1.w, ev[7], h1);
        h0 = fmaxf(h0, 0.0f);
        h1 = fmaxf(h1, 0.0f);

        // pack to tf32 fragment layout: uint2(h[k], h[k+4])
        float ph0 = __shfl_xor_sync(FULL, h0, 4);
        float ph1 = __shfl_xor_sync(FULL, h1, 4);
        if (!(lane & 4)) {
            int pos = (lane >> 3) * 4 + (lane & 3);
            As[row * ST2 + pos]      = make_uint2(f2tf32(h0), f2tf32(ph0));
            As[row * ST2 + 16 + pos] = make_uint2(f2tf32(h1), f2tf32(ph1));
        }
    }
    __syncthreads();

    // ---------------- Phase 2: in-block GEMM 64 x 512, 4 N-chunks ----------------
    int wm = (wid >> 2) * 32;        // 2 warps in M: 0, 32
    int wn = (wid & 3) * 32;         // 4 warps in N: 0,32,64,96 within chunk
    int g  = lane >> 2;
    int tg = lane & 3;

    #pragma unroll
    for (int it = 0; it < 4; ++it) {
        int bn = it * 128;

        // stage W2 chunk: 128 rows x 8 kk = 1024 tasks / 256 threads
        const float4* Wg = (const float4*)(W2 + (size_t)bn * 64);
        #pragma unroll
        for (int i = 0; i < 4; ++i) {
            int task = i * 256 + t;
            int rowN = task >> 3, kk = task & 7;
            float4 b0 = __ldg(Wg + rowN * 16 + kk * 2);
            float4 b1v = __ldg(Wg + rowN * 16 + kk * 2 + 1);
            uint2* pb = Bs + rowN * ST2 + kk * 4;
            pb[0] = make_uint2(f2tf32(b0.x), f2tf32(b1v.x));
            pb[1] = make_uint2(f2tf32(b0.y), f2tf32(b1v.y));
            pb[2] = make_uint2(f2tf32(b0.z), f2tf32(b1v.z));
            pb[3] = make_uint2(f2tf32(b0.w), f2tf32(b1v.w));
        }
        __syncthreads();

        float acc[2][4][4];
        #pragma unroll
        for (int f = 0; f < 2; ++f)
            #pragma unroll
            for (int j = 0; j < 4; ++j)
                #pragma unroll
                for (int q = 0; q < 4; ++q) acc[f][j][q] = 0.0f;

        #pragma unroll
        for (int kk = 0; kk < 8; ++kk) {
            int kb = kk * 4 + tg;
            uint2 va0 = As[(wm + g) * ST2 + kb];
            uint2 va1 = As[(wm + g + 8) * ST2 + kb];
            uint2 va2 = As[(wm + g + 16) * ST2 + kb];
            uint2 va3 = As[(wm + g + 24) * ST2 + kb];
            uint32_t a[2][4] = {
                { va0.x, va1.x, va0.y, va1.y },
                { va2.x, va3.x, va2.y, va3.y }
            };
            uint2 wb[4];
            #pragma unroll
            for (int j = 0; j < 4; ++j)
                wb[j] = Bs[(wn + j * 8 + g) * ST2 + kb];

            #pragma unroll
            for (int f = 0; f < 2; ++f)
                #pragma unroll
                for (int j = 0; j < 4; ++j)
                    asm volatile(
                        "mma.sync.aligned.m16n8k8.row.col.f32.tf32.tf32.f32 "
                        "{%0,%1,%2,%3}, {%4,%5,%6,%7}, {%8,%9}, {%0,%1,%2,%3};"
                        : "+f"(acc[f][j][0]), "+f"(acc[f][j][1]),
                          "+f"(acc[f][j][2]), "+f"(acc[f][j][3])
                        : "r"(a[f][0]), "r"(a[f][1]), "r"(a[f][2]), "r"(a[f][3]),
                          "r"(wb[j].x), "r"(wb[j].y));
        }

        // epilogue
        #pragma unroll
        for (int j = 0; j < 4; ++j) {
            int col = bn + wn + j * 8 + tg * 2;
            float2 bias = __ldg((const float2*)(b2 + col));
            #pragma unroll
            for (int f = 0; f < 2; ++f) {
                int row = bm + wm + f * 16 + g;
                float2 o0 = { acc[f][j][0] + bias.x, acc[f][j][1] + bias.y };
                float2 o1 = { acc[f][j][2] + bias.x, acc[f][j][3] + bias.y };
                *(float2*)(out + (size_t)row * 512 + col)       = o0;
                *(float2*)(out + (size_t)(row + 8) * 512 + col) = o1;
            }
        }
        __syncthreads();
    }
}

// ============================================================================
// Launch
// ============================================================================
extern "C" void kernel_launch(void* const* d_in, const int* in_sizes, int n_in,
                              void* d_out, int out_size) {
    const float* x   = (const float*)d_in[0];
    const float* ryt = (const float*)d_in[1];
    const float* rp  = (const float*)d_in[2];
    const float* W1  = (const float*)d_in[3];
    const float* b1  = (const float*)d_in[4];
    const float* W2  = (const float*)d_in[5];
    const float* b2  = (const float*)d_in[6];
    float* out = (float*)d_out;

    int rows = in_sizes[0] / 512;            // B*S = 16384

    const int smem = (64 + 128) * ST2 * (int)sizeof(uint2)   // As + Bs = 55296
                   + 64 * 16 * (int)sizeof(float)            // fs      =  4096
                   + 64 * (int)sizeof(float);                // cs
    cudaFuncSetAttribute(fused_kernel, cudaFuncAttributeMaxDynamicSharedMemorySize, smem);

    fused_kernel<<<rows / 64, 256, smem>>>(x, W1, b1, rp, ryt, W2, b2, out);
}